// round 17
// baseline (speedup 1.0000x reference)
#include <cuda_runtime.h>
#include <cuda_bf16.h>

#define BATCH 256
#define PPAIR 1024
#define TPTS  100
#define NGRID 65536
#define NB    (TPTS + 1)   // mid-buckets 0..100

// g_top zero-initialized at module load; K2 resets it to 0 each launch.
// Sentinel key = 0: inputs are in [0,1], so every real key enc(x), x in [-1,1],
// is >= enc(-1) = 0x407FFFFF > 0. dec0(0) maps back to -1e30.
__device__ uint2  g_top[BATCH * 4 * 128];   // [b][dim*2+side][bucket] (M1,M2)
__device__ float2 g_tr [BATCH * 2];         // [b][dim] = (tmin, tmax)

// order-preserving float <-> uint (monotone)
__device__ __forceinline__ unsigned enc(float f) {
    unsigned u = __float_as_uint(f);
    return (u >> 31) ? ~u : (u | 0x80000000u);
}
__device__ __forceinline__ float dec0(unsigned k) {
    if (k == 0u) return -1e30f;
    return __uint_as_float((k & 0x80000000u) ? (k ^ 0x80000000u) : ~k);
}
__device__ __forceinline__ uint2 top2_merge(uint2 a, uint2 b) {
    unsigned lo = umin(a.x, b.x);
    return make_uint2(umax(a.x, b.x), umax(lo, umax(a.y, b.y)));
}

// ---- K0: t-range per (batch, dim); one warp each, no barriers --------------
__global__ __launch_bounds__(64, 16)
void trange_kernel(const float* __restrict__ inputs,
                   const int*   __restrict__ dim_idx,
                   const int*   __restrict__ birth_loc,
                   const int*   __restrict__ death_loc)
{
    const int b    = blockIdx.x;
    const int w    = threadIdx.x >> 5;     // dim 0 or 1
    const int lane = threadIdx.x & 31;
    const int* __restrict__ di = dim_idx + b * PPAIR;

    int tot = 0, p0 = -1, p1 = -1;
    for (int ck = 0; ck < 32 && tot < 2; ck++) {
        int d = di[ck * 32 + lane];
        unsigned m = __ballot_sync(0xffffffffu, d == w);
        if (m) {
            if (tot == 0) {
                p0 = ck * 32 + __ffs(m) - 1;
                unsigned m2 = m & (m - 1);
                if (m2) p1 = ck * 32 + __ffs(m2) - 1;
            } else {                        // tot == 1
                p1 = ck * 32 + __ffs(m) - 1;
            }
            tot += __popc(m);
        }
    }
    if (lane == 0) {
        float tmin = 0.0f, tmax = 0.0f;
        if (p0 >= 0) {
            const int base = b * PPAIR;
            const float* __restrict__ row = inputs + ((size_t)b << 16);
            tmin = __ldg(row + __ldg(birth_loc + base + p0));
            tmax = __ldg(row + __ldg(death_loc + base + p0));
            if (p1 >= 0) {
                tmin = fminf(tmin, __ldg(row + __ldg(birth_loc + base + p1)));
                tmax = fmaxf(tmax, __ldg(row + __ldg(death_loc + base + p1)));
            }
        }
        g_tr[b * 2 + w] = make_float2(tmin, tmax);
    }
}

// ---- K1: gather + bucket + global atomic top2; barrier-free ---------------
__global__ __launch_bounds__(256, 8)
void scatter_kernel(const float* __restrict__ inputs,
                    const int*   __restrict__ dim_idx,
                    const int*   __restrict__ birth_loc,
                    const int*   __restrict__ death_loc)
{
    const int idx = blockIdx.x * 256 + threadIdx.x;   // 0 .. B*P-1
    const int bt  = idx >> 10;
    const int dm  = dim_idx  [idx];
    const int bl  = birth_loc[idx];
    const int dl  = death_loc[idx];
    const float* __restrict__ row = inputs + ((size_t)bt << 16);
    const float vb = __ldg(row + bl);
    const float vd = __ldg(row + dl);

    const float2 tr = g_tr[bt * 2 + dm];
    const float mid  = 0.5f * (vb + vd);
    const float num  = mid - tr.x;
    const float step = (tr.y - tr.x) * (1.0f / (float)(TPTS - 1));
    int c;
    if (num <= 0.0f)       c = 0;
    else if (step <= 0.0f) c = NB - 1;
    else                   c = min(NB - 1, (int)ceilf(num / step));

    // exact running top-2 (order-independent): M1=max; M2=max of min(k, prefix-max)
    const unsigned kd = enc(vd);       // A side: death values
    const unsigned kb = enc(-vb);      // B side: -birth values
    uint2* A  = &g_top[((bt * 4) + dm * 2 + 0) * 128 + c];
    uint2* Bs = &g_top[((bt * 4) + dm * 2 + 1) * 128 + c];
    unsigned oldA = atomicMax(&A->x, kd);
    atomicMax(&A->y, umin(kd, oldA));
    unsigned oldB = atomicMax(&Bs->x, kb);
    atomicMax(&Bs->y, umin(kb, oldB));
}

// ---- K2: per-batch scan + finalize + reset g_top --------------------------
__global__ __launch_bounds__(256, 8)
void finalize_kernel(float* __restrict__ land,    // [B, 2, T, 2]
                     float* __restrict__ trange)  // [B, 4]
{
    __shared__ uint2    s_top[4][128];
    __shared__ unsigned s_max[2];

    const int b    = blockIdx.x;
    const int tid  = threadIdx.x;
    const int lane = tid & 31;
    const int w    = tid >> 5;

    uint2* __restrict__ g = g_top + b * 512;
    s_top[tid >> 7][tid & 127] = g[tid];
    s_top[(tid + 256) >> 7][tid & 127] = g[tid + 256];
    if (tid < 2) s_max[tid] = 0u;
    __syncthreads();                                            // (1)

    // 4 warps: in-register top2 scan (side0 prefix asc, side1 suffix desc)
    if (w < 4) {
        const int side = w & 1;
        uint2 rr[4];
        uint2 acc = make_uint2(0u, 0u);
        #pragma unroll
        for (int k = 0; k < 4; k++) {
            int j = side ? 127 - (lane * 4 + k) : (lane * 4 + k);
            acc = top2_merge(acc, s_top[w][j]);
            rr[k] = acc;
        }
        uint2 sc = acc;
        #pragma unroll
        for (int o = 1; o < 32; o <<= 1) {
            uint2 ox;
            ox.x = __shfl_up_sync(0xffffffffu, sc.x, o);
            ox.y = __shfl_up_sync(0xffffffffu, sc.y, o);
            if (lane >= o) sc = top2_merge(sc, ox);
        }
        uint2 ex;
        ex.x = __shfl_up_sync(0xffffffffu, sc.x, 1);
        ex.y = __shfl_up_sync(0xffffffffu, sc.y, 1);
        if (lane == 0) ex = make_uint2(0u, 0u);
        #pragma unroll
        for (int k = 0; k < 4; k++) {
            int j = side ? 127 - (lane * 4 + k) : (lane * 4 + k);
            s_top[w][j] = top2_merge(ex, rr[k]);   // in-place: own entries only
        }
    }
    __syncthreads();                                            // (2)

    // finalize per (dim, t)
    {
        const int dim = tid >> 7;
        const int t   = tid & 127;
        float m1 = 0.0f;
        if (t < TPTS) {
            const float2 tr = g_tr[b * 2 + dim];
            const float tv  = tr.x + (tr.y - tr.x) *
                              ((float)t * (1.0f / (float)(TPTS - 1)));
            uint2 A  = s_top[dim * 2 + 0][t];       // mids in buckets 0..t
            uint2 Bs = s_top[dim * 2 + 1][t + 1];   // mids in buckets t+1..
            float vA1 = dec0(A.x) - tv,  vA2 = dec0(A.y) - tv;   // d - tv
            float vB1 = dec0(Bs.x) + tv, vB2 = dec0(Bs.y) + tv;  // tv - b
            m1 = fmaxf(0.0f, fmaxf(vA1, vB1));
            float s2 = fmaxf(fminf(vA1, vB1), (vA1 >= vB1) ? vA2 : vB2);
            float m2 = fmaxf(0.0f, s2);
            *(float2*)&land[((size_t)(b * 2 + dim) * TPTS + t) * 2] =
                make_float2(m1, m2);
        }
        unsigned wm = __reduce_max_sync(0xffffffffu, __float_as_uint(m1));
        if (lane == 0) atomicMax(&s_max[tid >> 7], wm);  // m1 >= 0: bit order OK
    }
    __syncthreads();                                            // (3)

    // reset scratch for next launch + t-range outputs
    const uint2 z = make_uint2(0u, 0u);
    g[tid] = z;
    g[tid + 256] = z;
    if (tid < 2) {
        // cnt==0 implies m1==0 everywhere, so nz == (max m1 > 0)
        bool nz = (s_max[tid] != 0u);
        const float2 tr = g_tr[b * 2 + tid];
        trange[b * 4 + 2 * tid + 0] = nz ? tr.x : 0.0f;
        trange[b * 4 + 2 * tid + 1] = nz ? tr.y : 0.0f;
    }
}

extern "C" void kernel_launch(void* const* d_in, const int* in_sizes, int n_in,
                              void* d_out, int out_size) {
    const float* inputs    = (const float*)d_in[0];
    const int*   dim_idx   = (const int*)  d_in[1];
    const int*   birth_loc = (const int*)  d_in[2];
    const int*   death_loc = (const int*)  d_in[3];

    float* land   = (float*)d_out;                        // B*2*T*2 = 102400
    float* trange = land + (size_t)BATCH * 2 * TPTS * 2;  // B*4     = 1024

    trange_kernel <<<BATCH, 64>>>(inputs, dim_idx, birth_loc, death_loc);
    scatter_kernel<<<(BATCH * PPAIR) / 256, 256>>>(inputs, dim_idx,
                                                   birth_loc, death_loc);
    finalize_kernel<<<BATCH, 256>>>(land, trange);
}